// round 8
// baseline (speedup 1.0000x reference)
#include <cuda_runtime.h>

// ---------------------------------------------------------------------------
// NextVisitTime attention, 2 launches:
//   pre1 : W2 (inline v), ts (m-trick), K2 (inline k) from raw inputs.
//   main : per block = 64 rows: inline us[b] = upt[user[b]] @ K2, masked
//          softmax from (us + ts[hour]), then [64x96]@[96x256] fp32 GEMM via
//          FFMA2. 512 threads, warps tiled 4 rowgroups x 4 colgroups; att
//          stored twice (+64B bank shift) so 2-addr LDS.128 reads are 1 wf.
// ---------------------------------------------------------------------------

#define T_SLOTS 24
#define D_MODEL 256
#define B_BATCH 512
#define N_ROWS  65536
#define J_DIM   96
#define HD      64

__device__ float g_ts[T_SLOTS * J_DIM];
__device__ float g_K2[D_MODEL * J_DIM];      // scale folded in
__device__ float g_W2[J_DIM * D_MODEL];

typedef unsigned long long u64;

__device__ __forceinline__ u64 pack_dup(float x) {
    u64 r; asm("mov.b64 %0, {%1, %1};" : "=l"(r) : "f"(x)); return r;
}
__device__ __forceinline__ u64 pack2(float x, float y) {
    u64 r; asm("mov.b64 %0, {%1, %2};" : "=l"(r) : "f"(x), "f"(y)); return r;
}
__device__ __forceinline__ void fma2(u64 &c, u64 a, u64 b) {
    asm("fma.rn.f32x2 %0, %1, %2, %0;" : "+l"(c) : "l"(a), "l"(b));
}
__device__ __forceinline__ float2 unpack2(u64 v) {
    float2 r; asm("mov.b64 {%0, %1}, %2;" : "=f"(r.x), "=f"(r.y) : "l"(v)); return r;
}

// ===========================================================================
// PRE1: 216 independent blocks (unchanged from round 7 — verified correct).
// ===========================================================================
__global__ __launch_bounds__(256) void pre1_kernel(
    const float* __restrict__ ts_emb,
    const float* __restrict__ Wq, const float* __restrict__ bq,
    const float* __restrict__ Wk, const float* __restrict__ bk,
    const float* __restrict__ Wv, const float* __restrict__ bv,
    const float* __restrict__ Wu)
{
    int bx = blockIdx.x, tid = threadIdx.x;

    if (bx < 96) {
        int j = bx, h = j / T_SLOTS, t = j % T_SLOTS;
        __shared__ __align__(16) float semb[D_MODEL];
        __shared__ __align__(16) float sv[HD];
        semb[tid] = ts_emb[t * D_MODEL + tid];
        __syncthreads();
        float a[8];
        a[0] = bv[tid];
        #pragma unroll
        for (int i = 1; i < 8; i++) a[i] = 0.f;
        #pragma unroll 4
        for (int c = 0; c < D_MODEL; c += 8) {
            #pragma unroll
            for (int u = 0; u < 8; u++)
                a[u] = fmaf(semb[c + u], Wv[(c + u) * D_MODEL + tid], a[u]);
        }
        float vd = ((a[0]+a[1])+(a[2]+a[3])) + ((a[4]+a[5])+(a[6]+a[7]));
        if (tid >= h * HD && tid < h * HD + HD) sv[tid - h * HD] = vd;
        __syncthreads();
        float b[8];
        #pragma unroll
        for (int i = 0; i < 8; i++) b[i] = 0.f;
        #pragma unroll 2
        for (int e = 0; e < HD; e += 8) {
            #pragma unroll
            for (int u = 0; u < 8; u++)
                b[u] = fmaf(sv[e + u], Wu[(h * HD + e + u) * D_MODEL + tid], b[u]);
        }
        g_W2[j * D_MODEL + tid] =
            ((b[0]+b[1])+(b[2]+b[3])) + ((b[4]+b[5])+(b[6]+b[7]));

    } else if (bx < 120) {
        int th = bx - 96;
        __shared__ __align__(16) float semb[D_MODEL];
        __shared__ __align__(16) float stq[D_MODEL];
        __shared__ __align__(16) float smm[D_MODEL * 4];
        __shared__ float stbk[4];
        semb[tid] = ts_emb[th * D_MODEL + tid];
        __syncthreads();
        float a[8];
        a[0] = bq[tid];
        #pragma unroll
        for (int i = 1; i < 8; i++) a[i] = 0.f;
        #pragma unroll 4
        for (int c = 0; c < D_MODEL; c += 8) {
            #pragma unroll
            for (int u = 0; u < 8; u++)
                a[u] = fmaf(semb[c + u], Wq[(D_MODEL + c + u) * D_MODEL + tid], a[u]);
        }
        stq[tid] = ((a[0]+a[1])+(a[2]+a[3])) + ((a[4]+a[5])+(a[6]+a[7]));
        __syncthreads();
        {
            const float4* wr = (const float4*)(Wk + (size_t)tid * D_MODEL);
            const float4* q4 = (const float4*)stq;
            #pragma unroll
            for (int h = 0; h < 4; h++) {
                float s0 = 0.f, s1 = 0.f, s2 = 0.f, s3 = 0.f;
                #pragma unroll 4
                for (int e4 = h * 16; e4 < h * 16 + 16; e4++) {
                    float4 wv = wr[e4], qv = q4[e4];
                    s0 = fmaf(qv.x, wv.x, s0); s1 = fmaf(qv.y, wv.y, s1);
                    s2 = fmaf(qv.z, wv.z, s2); s3 = fmaf(qv.w, wv.w, s3);
                }
                smm[tid * 4 + h] = (s0 + s1) + (s2 + s3);
            }
        }
        if (tid < 4) {
            float s = 0.f;
            for (int e = 0; e < HD; e++)
                s = fmaf(stq[tid * HD + e], bk[tid * HD + e], s);
            stbk[tid] = s;
        }
        __syncthreads();
        if (tid < J_DIM) {
            int h = tid / T_SLOTS, t = tid % T_SLOTS;
            const float* er = ts_emb + t * D_MODEL;
            float s0 = 0.f, s1 = 0.f, s2 = 0.f, s3 = 0.f;
            #pragma unroll 8
            for (int c = 0; c < D_MODEL; c += 4) {
                s0 = fmaf(er[c+0], smm[(c+0)*4 + h], s0);
                s1 = fmaf(er[c+1], smm[(c+1)*4 + h], s1);
                s2 = fmaf(er[c+2], smm[(c+2)*4 + h], s2);
                s3 = fmaf(er[c+3], smm[(c+3)*4 + h], s3);
            }
            g_ts[th * J_DIM + tid] =
                (((s0 + s1) + (s2 + s3)) + stbk[h]) * 0.125f;
        }

    } else {
        int j = bx - 120;
        int h = j / T_SLOTS, t = j % T_SLOTS;
        __shared__ __align__(16) float semb[D_MODEL];
        __shared__ float part[4][HD];
        __shared__ __align__(16) float kh[HD];
        semb[tid] = ts_emb[t * D_MODEL + tid];
        __syncthreads();
        {
            int e = tid & 63, ch = tid >> 6;
            const float* wk = Wk + (size_t)(ch * 64) * D_MODEL + h * HD + e;
            float s = 0.f;
            #pragma unroll 8
            for (int cc = 0; cc < 64; cc++)
                s = fmaf(semb[ch * 64 + cc], wk[cc * D_MODEL], s);
            part[ch][e] = s;
        }
        __syncthreads();
        if (tid < HD)
            kh[tid] = ((part[0][tid] + part[1][tid]) +
                       (part[2][tid] + part[3][tid])) + bk[h * HD + tid];
        __syncthreads();
        {
            const float4* wq = (const float4*)(Wq + (size_t)tid * D_MODEL + h * HD);
            const float4* k4 = (const float4*)kh;
            float s0 = 0.f, s1 = 0.f, s2 = 0.f, s3 = 0.f;
            #pragma unroll
            for (int e4 = 0; e4 < HD / 4; e4++) {
                float4 wv = wq[e4], kv = k4[e4];
                s0 = fmaf(wv.x, kv.x, s0); s1 = fmaf(wv.y, kv.y, s1);
                s2 = fmaf(wv.z, kv.z, s2); s3 = fmaf(wv.w, kv.w, s3);
            }
            g_K2[tid * J_DIM + j] = ((s0 + s1) + (s2 + s3)) * 0.125f;
        }
    }
}

// ===========================================================================
// MAIN: 512 threads, 64 rows/block, 1024 blocks.
// SMEM floats: W2 24576 | attA 64x98 u64 | pad 16 | attB 64x98 u64 | ts | us
// attB base is +64B relative to attA bank phase shifted by row delta 8 so
// lane-half pair reads (row r from A, row r+8 from B) never bank-conflict.
// ===========================================================================
#define SM_W2       0
#define ATT_PITCH64 98
#define ATT_F       (64 * ATT_PITCH64 * 2)            // 12544 floats per copy
#define SM_ATTA     24576
#define SM_ATTB     (SM_ATTA + ATT_F + 16)            // 37136 (+64B shift)
#define SM_TS       (SM_ATTB + ATT_F)                 // 49680
#define SM_US       (SM_TS + T_SLOTS * J_DIM)         // 51984
#define SM_FLOATS   (SM_US + J_DIM)                   // 52080
#define SM_BYTES    (SM_FLOATS * 4)                   // 208320

__global__ __launch_bounds__(512, 1) void main_kernel(
    const int* __restrict__ hour, const int* __restrict__ hmask,
    const int* __restrict__ user, const float* __restrict__ upt,
    const float* __restrict__ bu, float* __restrict__ out)
{
    extern __shared__ float sm[];
    float* sW2  = sm + SM_W2;
    u64*   attA = (u64*)(sm + SM_ATTA);
    u64*   attB = (u64*)(sm + SM_ATTB);
    float* sTs  = sm + SM_TS;
    float* sUs  = sm + SM_US;

    int tid = threadIdx.x;
    int n0  = blockIdx.x * 64;
    int b   = n0 >> 7;                 // 64 | 128 -> one batch row per block

    // cooperative loads (W2, ts) + inline us[b] = upt[user[b]] @ K2
    {
        const float4* s1 = (const float4*)g_W2;
        float4* d1 = (float4*)sW2;
        #pragma unroll
        for (int i = 0; i < 12; i++) d1[tid + i * 512] = s1[tid + i * 512];
        const float4* s2 = (const float4*)g_ts;
        float4* d2 = (float4*)sTs;
        for (int i = tid; i < (T_SLOTS * J_DIM) / 4; i += 512) d2[i] = s2[i];
    }
    if (tid < J_DIM) {
        const float* ur = upt + (size_t)__ldg(user + b) * D_MODEL;
        const float* kc = g_K2 + tid;
        float s0 = 0.f, s1 = 0.f, s2 = 0.f, s3 = 0.f;
        #pragma unroll 4
        for (int c = 0; c < D_MODEL; c += 4) {
            s0 = fmaf(__ldg(ur + c + 0), __ldg(kc + (c + 0) * J_DIM), s0);
            s1 = fmaf(__ldg(ur + c + 1), __ldg(kc + (c + 1) * J_DIM), s1);
            s2 = fmaf(__ldg(ur + c + 2), __ldg(kc + (c + 2) * J_DIM), s2);
            s3 = fmaf(__ldg(ur + c + 3), __ldg(kc + (c + 3) * J_DIM), s3);
        }
        sUs[tid] = (s0 + s1) + (s2 + s3);
    }
    __syncthreads();

    // ---- phase 1: threads [0,256): one (row, head) softmax, dual-stored ----
    if (tid < 256) {
        int r = tid >> 2, h = tid & 3;
        int n = n0 + r;
        int hh = __ldg(hour + n);
        int msk[T_SLOTS];
        const int4* mp = (const int4*)(hmask + (size_t)n * T_SLOTS);
        #pragma unroll
        for (int i = 0; i < 6; i++) {
            int4 q = mp[i];
            msk[4*i] = q.x; msk[4*i+1] = q.y; msk[4*i+2] = q.z; msk[4*i+3] = q.w;
        }
        const float* usb = sUs + h * T_SLOTS;
        const float* tsb = sTs + hh * J_DIM + h * T_SLOTS;
        float sc[T_SLOTS];
        float mx = -3.0e38f;
        #pragma unroll
        for (int t = 0; t < T_SLOTS; t++) {
            sc[t] = msk[t] ? -1e9f : (usb[t] + tsb[t]);
            mx = fmaxf(mx, sc[t]);
        }
        float s = 0.0f;
        #pragma unroll
        for (int t = 0; t < T_SLOTS; t++) {
            float e = __expf(sc[t] - mx);
            sc[t] = e; s += e;
        }
        float inv = 1.0f / s;
        u64* arA = attA + r * ATT_PITCH64 + h * T_SLOTS;
        u64* arB = attB + r * ATT_PITCH64 + h * T_SLOTS;
        #pragma unroll
        for (int t = 0; t < T_SLOTS; t++) {
            u64 d = pack_dup(sc[t] * inv);
            arA[t] = d; arB[t] = d;
        }
    }
    __syncthreads();

    // ---- phase 2: [64 x 96] @ [96 x 256] ----
    // Warp w: rowgroup rg = w>>2 (16 rows), colgroup cg = w&3 (64 f32 cols).
    // Thread: 8 rows (lane half), 4 f32 cols (u128 col cb).
    int w  = tid >> 5, l = tid & 31;
    int rg = w >> 2, cg = w & 3;
    int hf = l >> 4;                    // lane half -> +8 rows, copy B
    int r0 = rg * 16 + hf * 8;
    int cb = cg * 16 + (l & 15);        // u128 col (f32 cols 4cb..4cb+3)

    u64 acc[8][2];
    {
        float4 bv = __ldg((const float4*)bu + cb);
        u64 blo = pack2(bv.x, bv.y), bhi = pack2(bv.z, bv.w);
        #pragma unroll
        for (int rr = 0; rr < 8; rr++) { acc[rr][0] = blo; acc[rr][1] = bhi; }
    }
    const ulonglong2* w2p = (const ulonglong2*)sW2;   // 64 u128 per j-row
    const u64* ap = (hf ? attB : attA) + r0 * ATT_PITCH64;
    #pragma unroll 2
    for (int j = 0; j < J_DIM; j += 2) {
        ulonglong2 w0 = w2p[j * 64 + cb];
        ulonglong2 w1 = w2p[(j + 1) * 64 + cb];
        #pragma unroll
        for (int rr = 0; rr < 8; rr++) {
            ulonglong2 a = *(const ulonglong2*)(ap + rr * ATT_PITCH64 + j);
            fma2(acc[rr][0], a.x, w0.x);
            fma2(acc[rr][1], a.x, w0.y);
            fma2(acc[rr][0], a.y, w1.x);
            fma2(acc[rr][1], a.y, w1.y);
        }
    }
    #pragma unroll
    for (int rr = 0; rr < 8; rr++) {
        float2 lo = unpack2(acc[rr][0]);
        float2 hi = unpack2(acc[rr][1]);
        ((float4*)(out + (size_t)(n0 + r0 + rr) * D_MODEL))[cb] =
            make_float4(lo.x, lo.y, hi.x, hi.y);
    }
}

extern "C" void kernel_launch(void* const* d_in, const int* in_sizes, int n_in,
                              void* d_out, int out_size) {
    const float* ts_emb = (const float*)d_in[0];
    const int*   user   = (const int*)  d_in[1];
    const int*   hour   = (const int*)  d_in[2];
    const int*   hmask  = (const int*)  d_in[3];
    const float* upt    = (const float*)d_in[4];
    const float* Wq     = (const float*)d_in[5];
    const float* bq     = (const float*)d_in[6];
    const float* Wk     = (const float*)d_in[7];
    const float* bk     = (const float*)d_in[8];
    const float* Wv     = (const float*)d_in[9];
    const float* bv     = (const float*)d_in[10];
    const float* Wu     = (const float*)d_in[11];
    const float* bu     = (const float*)d_in[12];
    float* out = (float*)d_out;

    pre1_kernel<<<216, 256>>>(ts_emb, Wq, bq, Wk, bk, Wv, bv, Wu);

    cudaFuncSetAttribute(main_kernel, cudaFuncAttributeMaxDynamicSharedMemorySize, SM_BYTES);
    main_kernel<<<N_ROWS / 64, 512, SM_BYTES>>>(hour, hmask, user, upt, bu, out);
}

// round 9
// speedup vs baseline: 1.0600x; 1.0600x over previous
#include <cuda_runtime.h>

// ---------------------------------------------------------------------------
// NextVisitTime attention, 2 launches:
//   pre1 : W2 (inline v), ts (m-trick), K2 (inline k) from raw inputs.
//   main : per block = 64 rows: inline us[b] = upt[user[b]] @ K2, masked
//          softmax from (us + ts[hour]), then [64x96]@[96x256] fp32 GEMM via
//          FFMA2. 512 threads = 16 warps tiled 8 rowgroups x 2 colgroups:
//          att reads are single-address LDS.128 broadcasts, weight reads are
//          32-consecutive-u128 LDS.128 (conflict-free). 4 warps/SMSP.
// ---------------------------------------------------------------------------

#define T_SLOTS 24
#define D_MODEL 256
#define B_BATCH 512
#define N_ROWS  65536
#define J_DIM   96
#define HD      64

__device__ float g_ts[T_SLOTS * J_DIM];
__device__ float g_K2[D_MODEL * J_DIM];      // scale folded in
__device__ float g_W2[J_DIM * D_MODEL];

typedef unsigned long long u64;

__device__ __forceinline__ u64 pack_dup(float x) {
    u64 r; asm("mov.b64 %0, {%1, %1};" : "=l"(r) : "f"(x)); return r;
}
__device__ __forceinline__ u64 pack2(float x, float y) {
    u64 r; asm("mov.b64 %0, {%1, %2};" : "=l"(r) : "f"(x), "f"(y)); return r;
}
__device__ __forceinline__ void fma2(u64 &c, u64 a, u64 b) {
    asm("fma.rn.f32x2 %0, %1, %2, %0;" : "+l"(c) : "l"(a), "l"(b));
}
__device__ __forceinline__ float2 unpack2(u64 v) {
    float2 r; asm("mov.b64 {%0, %1}, %2;" : "=f"(r.x), "=f"(r.y) : "l"(v)); return r;
}

// ===========================================================================
// PRE1: 216 independent blocks (unchanged — verified correct, ~6 us).
// ===========================================================================
__global__ __launch_bounds__(256) void pre1_kernel(
    const float* __restrict__ ts_emb,
    const float* __restrict__ Wq, const float* __restrict__ bq,
    const float* __restrict__ Wk, const float* __restrict__ bk,
    const float* __restrict__ Wv, const float* __restrict__ bv,
    const float* __restrict__ Wu)
{
    int bx = blockIdx.x, tid = threadIdx.x;

    if (bx < 96) {
        int j = bx, h = j / T_SLOTS, t = j % T_SLOTS;
        __shared__ __align__(16) float semb[D_MODEL];
        __shared__ __align__(16) float sv[HD];
        semb[tid] = ts_emb[t * D_MODEL + tid];
        __syncthreads();
        float a[8];
        a[0] = bv[tid];
        #pragma unroll
        for (int i = 1; i < 8; i++) a[i] = 0.f;
        #pragma unroll 4
        for (int c = 0; c < D_MODEL; c += 8) {
            #pragma unroll
            for (int u = 0; u < 8; u++)
                a[u] = fmaf(semb[c + u], Wv[(c + u) * D_MODEL + tid], a[u]);
        }
        float vd = ((a[0]+a[1])+(a[2]+a[3])) + ((a[4]+a[5])+(a[6]+a[7]));
        if (tid >= h * HD && tid < h * HD + HD) sv[tid - h * HD] = vd;
        __syncthreads();
        float b[8];
        #pragma unroll
        for (int i = 0; i < 8; i++) b[i] = 0.f;
        #pragma unroll 2
        for (int e = 0; e < HD; e += 8) {
            #pragma unroll
            for (int u = 0; u < 8; u++)
                b[u] = fmaf(sv[e + u], Wu[(h * HD + e + u) * D_MODEL + tid], b[u]);
        }
        g_W2[j * D_MODEL + tid] =
            ((b[0]+b[1])+(b[2]+b[3])) + ((b[4]+b[5])+(b[6]+b[7]));

    } else if (bx < 120) {
        int th = bx - 96;
        __shared__ __align__(16) float semb[D_MODEL];
        __shared__ __align__(16) float stq[D_MODEL];
        __shared__ __align__(16) float smm[D_MODEL * 4];
        __shared__ float stbk[4];
        semb[tid] = ts_emb[th * D_MODEL + tid];
        __syncthreads();
        float a[8];
        a[0] = bq[tid];
        #pragma unroll
        for (int i = 1; i < 8; i++) a[i] = 0.f;
        #pragma unroll 4
        for (int c = 0; c < D_MODEL; c += 8) {
            #pragma unroll
            for (int u = 0; u < 8; u++)
                a[u] = fmaf(semb[c + u], Wq[(D_MODEL + c + u) * D_MODEL + tid], a[u]);
        }
        stq[tid] = ((a[0]+a[1])+(a[2]+a[3])) + ((a[4]+a[5])+(a[6]+a[7]));
        __syncthreads();
        {
            const float4* wr = (const float4*)(Wk + (size_t)tid * D_MODEL);
            const float4* q4 = (const float4*)stq;
            #pragma unroll
            for (int h = 0; h < 4; h++) {
                float s0 = 0.f, s1 = 0.f, s2 = 0.f, s3 = 0.f;
                #pragma unroll 4
                for (int e4 = h * 16; e4 < h * 16 + 16; e4++) {
                    float4 wv = wr[e4], qv = q4[e4];
                    s0 = fmaf(qv.x, wv.x, s0); s1 = fmaf(qv.y, wv.y, s1);
                    s2 = fmaf(qv.z, wv.z, s2); s3 = fmaf(qv.w, wv.w, s3);
                }
                smm[tid * 4 + h] = (s0 + s1) + (s2 + s3);
            }
        }
        if (tid < 4) {
            float s = 0.f;
            for (int e = 0; e < HD; e++)
                s = fmaf(stq[tid * HD + e], bk[tid * HD + e], s);
            stbk[tid] = s;
        }
        __syncthreads();
        if (tid < J_DIM) {
            int h = tid / T_SLOTS, t = tid % T_SLOTS;
            const float* er = ts_emb + t * D_MODEL;
            float s0 = 0.f, s1 = 0.f, s2 = 0.f, s3 = 0.f;
            #pragma unroll 8
            for (int c = 0; c < D_MODEL; c += 4) {
                s0 = fmaf(er[c+0], smm[(c+0)*4 + h], s0);
                s1 = fmaf(er[c+1], smm[(c+1)*4 + h], s1);
                s2 = fmaf(er[c+2], smm[(c+2)*4 + h], s2);
                s3 = fmaf(er[c+3], smm[(c+3)*4 + h], s3);
            }
            g_ts[th * J_DIM + tid] =
                (((s0 + s1) + (s2 + s3)) + stbk[h]) * 0.125f;
        }

    } else {
        int j = bx - 120;
        int h = j / T_SLOTS, t = j % T_SLOTS;
        __shared__ __align__(16) float semb[D_MODEL];
        __shared__ float part[4][HD];
        __shared__ __align__(16) float kh[HD];
        semb[tid] = ts_emb[t * D_MODEL + tid];
        __syncthreads();
        {
            int e = tid & 63, ch = tid >> 6;
            const float* wk = Wk + (size_t)(ch * 64) * D_MODEL + h * HD + e;
            float s = 0.f;
            #pragma unroll 8
            for (int cc = 0; cc < 64; cc++)
                s = fmaf(semb[ch * 64 + cc], wk[cc * D_MODEL], s);
            part[ch][e] = s;
        }
        __syncthreads();
        if (tid < HD)
            kh[tid] = ((part[0][tid] + part[1][tid]) +
                       (part[2][tid] + part[3][tid])) + bk[h * HD + tid];
        __syncthreads();
        {
            const float4* wq = (const float4*)(Wq + (size_t)tid * D_MODEL + h * HD);
            const float4* k4 = (const float4*)kh;
            float s0 = 0.f, s1 = 0.f, s2 = 0.f, s3 = 0.f;
            #pragma unroll
            for (int e4 = 0; e4 < HD / 4; e4++) {
                float4 wv = wq[e4], kv = k4[e4];
                s0 = fmaf(wv.x, kv.x, s0); s1 = fmaf(wv.y, kv.y, s1);
                s2 = fmaf(wv.z, kv.z, s2); s3 = fmaf(wv.w, kv.w, s3);
            }
            g_K2[tid * J_DIM + j] = ((s0 + s1) + (s2 + s3)) * 0.125f;
        }
    }
}

// ===========================================================================
// MAIN: 512 threads, 64 rows/block, 1024 blocks, single att copy.
// SMEM floats: W2 24576 | att 64 x 98 u64 (12544 f) | ts 2304 | us 96
// Phase 2: warp w -> rowgroup rg = w>>1 (8 rows), colgroup cg = w&1
// (128 f32 cols = 32 u128, one per lane). Per 2j per warp:
//   2 weight LDS.128 (32 consecutive u128, 4 wf each, conflict-free)
//   8 att LDS.128 (warp-uniform address -> broadcast, 1 wf each)
// -> 16 wf/warp/2j, 256 wf/SM/2j ~ 256 FMA cyc/2j: both pipes saturated,
//    4 warps/SMSP for latency hiding. acc = 16 u64 = 32 regs.
// ===========================================================================
#define SM_W2       0
#define ATT_PITCH64 98
#define SM_ATT      24576
#define SM_TS       (SM_ATT + 64 * ATT_PITCH64 * 2)  // 37120
#define SM_US       (SM_TS + T_SLOTS * J_DIM)        // 39424
#define SM_FLOATS   (SM_US + J_DIM)                  // 39520
#define SM_BYTES    (SM_FLOATS * 4)                  // 158080

__global__ __launch_bounds__(512, 1) void main_kernel(
    const int* __restrict__ hour, const int* __restrict__ hmask,
    const int* __restrict__ user, const float* __restrict__ upt,
    const float* __restrict__ bu, float* __restrict__ out)
{
    extern __shared__ float sm[];
    float* sW2  = sm + SM_W2;
    u64*   sAtt = (u64*)(sm + SM_ATT);
    float* sTs  = sm + SM_TS;
    float* sUs  = sm + SM_US;

    int tid = threadIdx.x;
    int n0  = blockIdx.x * 64;
    int b   = n0 >> 7;                 // 64 | 128 -> one batch row per block

    // cooperative loads (W2, ts) + inline us[b] = upt[user[b]] @ K2
    {
        const float4* s1 = (const float4*)g_W2;
        float4* d1 = (float4*)sW2;
        #pragma unroll
        for (int i = 0; i < 12; i++) d1[tid + i * 512] = s1[tid + i * 512];
        const float4* s2 = (const float4*)g_ts;
        float4* d2 = (float4*)sTs;
        for (int i = tid; i < (T_SLOTS * J_DIM) / 4; i += 512) d2[i] = s2[i];
    }
    if (tid < J_DIM) {
        const float* ur = upt + (size_t)__ldg(user + b) * D_MODEL;
        const float* kc = g_K2 + tid;
        float s0 = 0.f, s1 = 0.f, s2 = 0.f, s3 = 0.f;
        #pragma unroll 4
        for (int c = 0; c < D_MODEL; c += 4) {
            s0 = fmaf(__ldg(ur + c + 0), __ldg(kc + (c + 0) * J_DIM), s0);
            s1 = fmaf(__ldg(ur + c + 1), __ldg(kc + (c + 1) * J_DIM), s1);
            s2 = fmaf(__ldg(ur + c + 2), __ldg(kc + (c + 2) * J_DIM), s2);
            s3 = fmaf(__ldg(ur + c + 3), __ldg(kc + (c + 3) * J_DIM), s3);
        }
        sUs[tid] = (s0 + s1) + (s2 + s3);
    }
    __syncthreads();

    // ---- phase 1: threads [0,256): one (row, head) softmax, dup-stored ----
    if (tid < 256) {
        int r = tid >> 2, h = tid & 3;
        int n = n0 + r;
        int hh = __ldg(hour + n);
        int msk[T_SLOTS];
        const int4* mp = (const int4*)(hmask + (size_t)n * T_SLOTS);
        #pragma unroll
        for (int i = 0; i < 6; i++) {
            int4 q = mp[i];
            msk[4*i] = q.x; msk[4*i+1] = q.y; msk[4*i+2] = q.z; msk[4*i+3] = q.w;
        }
        const float* usb = sUs + h * T_SLOTS;
        const float* tsb = sTs + hh * J_DIM + h * T_SLOTS;
        float sc[T_SLOTS];
        float mx = -3.0e38f;
        #pragma unroll
        for (int t = 0; t < T_SLOTS; t++) {
            sc[t] = msk[t] ? -1e9f : (usb[t] + tsb[t]);
            mx = fmaxf(mx, sc[t]);
        }
        float s = 0.0f;
        #pragma unroll
        for (int t = 0; t < T_SLOTS; t++) {
            float e = __expf(sc[t] - mx);
            sc[t] = e; s += e;
        }
        float inv = 1.0f / s;
        u64* ar = sAtt + r * ATT_PITCH64 + h * T_SLOTS;
        #pragma unroll
        for (int t = 0; t < T_SLOTS; t++) ar[t] = pack_dup(sc[t] * inv);
    }
    __syncthreads();

    // ---- phase 2: [64 x 96] @ [96 x 256] ----
    int w  = tid >> 5, l = tid & 31;
    int rg = w >> 1, cg = w & 1;
    int r0 = rg * 8;
    int cb = cg * 32 + l;               // u128 col 0..63 (f32 cols 4cb..4cb+3)

    u64 acc[8][2];
    {
        float4 bv = __ldg((const float4*)bu + cb);
        u64 blo = pack2(bv.x, bv.y), bhi = pack2(bv.z, bv.w);
        #pragma unroll
        for (int rr = 0; rr < 8; rr++) { acc[rr][0] = blo; acc[rr][1] = bhi; }
    }
    const ulonglong2* w2p = (const ulonglong2*)sW2;   // 64 u128 per j-row
    const u64* ap = sAtt + r0 * ATT_PITCH64;
    #pragma unroll 4
    for (int j = 0; j < J_DIM; j += 2) {
        ulonglong2 w0 = w2p[j * 64 + cb];
        ulonglong2 w1 = w2p[(j + 1) * 64 + cb];
        #pragma unroll
        for (int rr = 0; rr < 8; rr++) {
            ulonglong2 a = *(const ulonglong2*)(ap + rr * ATT_PITCH64 + j);
            fma2(acc[rr][0], a.x, w0.x);
            fma2(acc[rr][1], a.x, w0.y);
            fma2(acc[rr][0], a.y, w1.x);
            fma2(acc[rr][1], a.y, w1.y);
        }
    }
    #pragma unroll
    for (int rr = 0; rr < 8; rr++) {
        float2 lo = unpack2(acc[rr][0]);
        float2 hi = unpack2(acc[rr][1]);
        ((float4*)(out + (size_t)(n0 + r0 + rr) * D_MODEL))[cb] =
            make_float4(lo.x, lo.y, hi.x, hi.y);
    }
}

extern "C" void kernel_launch(void* const* d_in, const int* in_sizes, int n_in,
                              void* d_out, int out_size) {
    const float* ts_emb = (const float*)d_in[0];
    const int*   user   = (const int*)  d_in[1];
    const int*   hour   = (const int*)  d_in[2];
    const int*   hmask  = (const int*)  d_in[3];
    const float* upt    = (const float*)d_in[4];
    const float* Wq     = (const float*)d_in[5];
    const float* bq     = (const float*)d_in[6];
    const float* Wk     = (const float*)d_in[7];
    const float* bk     = (const float*)d_in[8];
    const float* Wv     = (const float*)d_in[9];
    const float* bv     = (const float*)d_in[10];
    const float* Wu     = (const float*)d_in[11];
    const float* bu     = (const float*)d_in[12];
    float* out = (float*)d_out;

    pre1_kernel<<<216, 256>>>(ts_emb, Wq, bq, Wk, bk, Wv, bv, Wu);

    cudaFuncSetAttribute(main_kernel, cudaFuncAttributeMaxDynamicSharedMemorySize, SM_BYTES);
    main_kernel<<<N_ROWS / 64, 512, SM_BYTES>>>(hour, hmask, user, upt, bu, out);
}

// round 10
// speedup vs baseline: 1.1646x; 1.0987x over previous
#include <cuda_runtime.h>

// ---------------------------------------------------------------------------
// NextVisitTime attention, 2 launches:
//   pre1 : W2 j-PAIRS (inline v, 2 rows/block), ts (m-trick), K2 (inline k).
//   main : 64 rows/block: inline us[b] = upt[user[b]] @ K2, masked softmax,
//          then [64x96]@[96x256] fp32 GEMM via FFMA2 with j-pair packing:
//          acc u64 = (even-j sum, odd-j sum) per f32 col; att read as plain
//          warp-uniform LDS.64 pairs (1 wf), weights as LDS.128 pairs.
//          8 warps x (8 rows x 256 cols); FMA-bound by construction.
// ---------------------------------------------------------------------------

#define T_SLOTS 24
#define D_MODEL 256
#define B_BATCH 512
#define N_ROWS  65536
#define J_DIM   96
#define J2      48
#define HD      64

__device__ float g_ts [T_SLOTS * J_DIM];
__device__ float g_K2 [D_MODEL * J_DIM];             // scale folded in
__device__ unsigned long long g_W2p[J2 * D_MODEL];   // (W2[2k][c], W2[2k+1][c])

typedef unsigned long long u64;

__device__ __forceinline__ u64 pack2(float x, float y) {
    u64 r; asm("mov.b64 %0, {%1, %2};" : "=l"(r) : "f"(x), "f"(y)); return r;
}
__device__ __forceinline__ void fma2(u64 &c, u64 a, u64 b) {
    asm("fma.rn.f32x2 %0, %1, %2, %0;" : "+l"(c) : "l"(a), "l"(b));
}
__device__ __forceinline__ float2 unpack2(u64 v) {
    float2 r; asm("mov.b64 {%0, %1}, %2;" : "=f"(r.x), "=f"(r.y) : "l"(v)); return r;
}

// ===========================================================================
// PRE1: 168 independent blocks.
//   [0,48):   W2 pair row j2 = bx (rows 2bx, 2bx+1; same head, t and t+1)
//   [48,72):  ts row th (m-trick over Wk)
//   [72,168): K2 col j (inline k head slice)
// ===========================================================================
__global__ __launch_bounds__(256) void pre1_kernel(
    const float* __restrict__ ts_emb,
    const float* __restrict__ Wq, const float* __restrict__ bq,
    const float* __restrict__ Wk, const float* __restrict__ bk,
    const float* __restrict__ Wv, const float* __restrict__ bv,
    const float* __restrict__ Wu)
{
    int bx = blockIdx.x, tid = threadIdx.x;

    if (bx < 48) {
        // ---- W2 pair: rows j0=2bx, j1=2bx+1 (h shared, t0, t1=t0+1) ----
        int j0 = 2 * bx;
        int h = j0 / T_SLOTS, t0 = j0 % T_SLOTS, t1 = t0 + 1;
        __shared__ __align__(16) float semb0[D_MODEL], semb1[D_MODEL];
        __shared__ __align__(16) float sv0[HD], sv1[HD];
        semb0[tid] = ts_emb[t0 * D_MODEL + tid];
        semb1[tid] = ts_emb[t1 * D_MODEL + tid];
        __syncthreads();
        // v0[d], v1[d]: share Wv column loads
        float a0[4], a1[4];
        a0[0] = bv[tid]; a1[0] = a0[0];
        #pragma unroll
        for (int i = 1; i < 4; i++) { a0[i] = 0.f; a1[i] = 0.f; }
        #pragma unroll 4
        for (int c = 0; c < D_MODEL; c += 4) {
            #pragma unroll
            for (int u = 0; u < 4; u++) {
                float wv = Wv[(c + u) * D_MODEL + tid];
                a0[u] = fmaf(semb0[c + u], wv, a0[u]);
                a1[u] = fmaf(semb1[c + u], wv, a1[u]);
            }
        }
        float v0 = (a0[0] + a0[1]) + (a0[2] + a0[3]);
        float v1 = (a1[0] + a1[1]) + (a1[2] + a1[3]);
        if (tid >= h * HD && tid < h * HD + HD) {
            sv0[tid - h * HD] = v0;
            sv1[tid - h * HD] = v1;
        }
        __syncthreads();
        float b0[4], b1[4];
        #pragma unroll
        for (int i = 0; i < 4; i++) { b0[i] = 0.f; b1[i] = 0.f; }
        #pragma unroll 4
        for (int e = 0; e < HD; e += 4) {
            #pragma unroll
            for (int u = 0; u < 4; u++) {
                float wu = Wu[(h * HD + e + u) * D_MODEL + tid];
                b0[u] = fmaf(sv0[e + u], wu, b0[u]);
                b1[u] = fmaf(sv1[e + u], wu, b1[u]);
            }
        }
        float w0 = (b0[0] + b0[1]) + (b0[2] + b0[3]);
        float w1 = (b1[0] + b1[1]) + (b1[2] + b1[3]);
        g_W2p[bx * D_MODEL + tid] = pack2(w0, w1);

    } else if (bx < 72) {
        // ---- ts[th][h*24+t] = 0.125*(sum_c emb[t,c]*m[c,h] + tq.bk_h) ----
        int th = bx - 48;
        __shared__ __align__(16) float semb[D_MODEL];
        __shared__ __align__(16) float stq[D_MODEL];
        __shared__ __align__(16) float smm[D_MODEL * 4];
        __shared__ float stbk[4];
        semb[tid] = ts_emb[th * D_MODEL + tid];
        __syncthreads();
        float a[8];
        a[0] = bq[tid];
        #pragma unroll
        for (int i = 1; i < 8; i++) a[i] = 0.f;
        #pragma unroll 4
        for (int c = 0; c < D_MODEL; c += 8) {
            #pragma unroll
            for (int u = 0; u < 8; u++)
                a[u] = fmaf(semb[c + u], Wq[(D_MODEL + c + u) * D_MODEL + tid], a[u]);
        }
        stq[tid] = ((a[0]+a[1])+(a[2]+a[3])) + ((a[4]+a[5])+(a[6]+a[7]));
        __syncthreads();
        {
            const float4* wr = (const float4*)(Wk + (size_t)tid * D_MODEL);
            const float4* q4 = (const float4*)stq;
            #pragma unroll
            for (int h = 0; h < 4; h++) {
                float s0 = 0.f, s1 = 0.f, s2 = 0.f, s3 = 0.f;
                #pragma unroll 4
                for (int e4 = h * 16; e4 < h * 16 + 16; e4++) {
                    float4 wv = wr[e4], qv = q4[e4];
                    s0 = fmaf(qv.x, wv.x, s0); s1 = fmaf(qv.y, wv.y, s1);
                    s2 = fmaf(qv.z, wv.z, s2); s3 = fmaf(qv.w, wv.w, s3);
                }
                smm[tid * 4 + h] = (s0 + s1) + (s2 + s3);
            }
        }
        if (tid < 4) {
            float s = 0.f;
            for (int e = 0; e < HD; e++)
                s = fmaf(stq[tid * HD + e], bk[tid * HD + e], s);
            stbk[tid] = s;
        }
        __syncthreads();
        if (tid < J_DIM) {
            int h = tid / T_SLOTS, t = tid % T_SLOTS;
            const float* er = ts_emb + t * D_MODEL;
            float s0 = 0.f, s1 = 0.f, s2 = 0.f, s3 = 0.f;
            #pragma unroll 8
            for (int c = 0; c < D_MODEL; c += 4) {
                s0 = fmaf(er[c+0], smm[(c+0)*4 + h], s0);
                s1 = fmaf(er[c+1], smm[(c+1)*4 + h], s1);
                s2 = fmaf(er[c+2], smm[(c+2)*4 + h], s2);
                s3 = fmaf(er[c+3], smm[(c+3)*4 + h], s3);
            }
            g_ts[th * J_DIM + tid] =
                (((s0 + s1) + (s2 + s3)) + stbk[h]) * 0.125f;
        }

    } else {
        // ---- K2[c][j] = 0.125 * sum_e Wq0[c,h64+e] * k[t,h64+e] ----
        int j = bx - 72;
        int h = j / T_SLOTS, t = j % T_SLOTS;
        __shared__ __align__(16) float semb[D_MODEL];
        __shared__ float part[4][HD];
        __shared__ __align__(16) float kh[HD];
        semb[tid] = ts_emb[t * D_MODEL + tid];
        __syncthreads();
        {
            int e = tid & 63, ch = tid >> 6;
            const float* wk = Wk + (size_t)(ch * 64) * D_MODEL + h * HD + e;
            float s = 0.f;
            #pragma unroll 8
            for (int cc = 0; cc < 64; cc++)
                s = fmaf(semb[ch * 64 + cc], wk[cc * D_MODEL], s);
            part[ch][e] = s;
        }
        __syncthreads();
        if (tid < HD)
            kh[tid] = ((part[0][tid] + part[1][tid]) +
                       (part[2][tid] + part[3][tid])) + bk[h * HD + tid];
        __syncthreads();
        {
            const float4* wq = (const float4*)(Wq + (size_t)tid * D_MODEL + h * HD);
            const float4* k4 = (const float4*)kh;
            float s0 = 0.f, s1 = 0.f, s2 = 0.f, s3 = 0.f;
            #pragma unroll
            for (int e4 = 0; e4 < HD / 4; e4++) {
                float4 wv = wq[e4], kv = k4[e4];
                s0 = fmaf(wv.x, kv.x, s0); s1 = fmaf(wv.y, kv.y, s1);
                s2 = fmaf(wv.z, kv.z, s2); s3 = fmaf(wv.w, kv.w, s3);
            }
            g_K2[tid * J_DIM + j] = ((s0 + s1) + (s2 + s3)) * 0.125f;
        }
    }
}

// ===========================================================================
// MAIN: 256 threads, 64 rows/block, 1024 blocks.
// SMEM floats: W2p 24576 | att u64 64 x 49 (6272 f) | ts 2304 | us 96
// Phase 2: warp w -> rows [8w, 8w+8), all 256 cols. Thread: 8 rows x 8 cols
// (cols 2l,2l+1 + {0,64,128,192}). Per j2 per warp: 8 warp-uniform LDS.64
// att pairs (1 wf each) + 4 LDS.128 weight pairs (4 wf) = 24 wf;
// 192 wf/SM/j2 < 256 FMA cyc/SMSP/j2 -> FMA-bound. acc = 64 u64.
// ===========================================================================
#define ATT_P     49                                 // u64 pitch per row
#define SM_W2P    0
#define SM_ATT    24576
#define SM_TS     (SM_ATT + 64 * ATT_P * 2)          // 30848
#define SM_US     (SM_TS + T_SLOTS * J_DIM)          // 33152
#define SM_FLOATS (SM_US + J_DIM)                    // 33248
#define SM_BYTES  (SM_FLOATS * 4)                    // 132992

__global__ __launch_bounds__(256, 1) void main_kernel(
    const int* __restrict__ hour, const int* __restrict__ hmask,
    const int* __restrict__ user, const float* __restrict__ upt,
    const float* __restrict__ bu, float* __restrict__ out)
{
    extern __shared__ float sm[];
    float* sW2  = sm + SM_W2P;
    u64*   sAtt = (u64*)(sm + SM_ATT);
    float* sTs  = sm + SM_TS;
    float* sUs  = sm + SM_US;

    int tid = threadIdx.x;
    int n0  = blockIdx.x * 64;
    int b   = n0 >> 7;                 // 64 | 128 -> one batch row per block

    // cooperative loads (W2p, ts) + inline us[b] = upt[user[b]] @ K2
    {
        const float4* s1 = (const float4*)g_W2p;
        float4* d1 = (float4*)sW2;
        #pragma unroll
        for (int i = 0; i < 24; i++) d1[tid + i * 256] = s1[tid + i * 256];
        const float4* s2 = (const float4*)g_ts;
        float4* d2 = (float4*)sTs;
        for (int i = tid; i < (T_SLOTS * J_DIM) / 4; i += 256) d2[i] = s2[i];
    }
    if (tid < J_DIM) {
        const float* ur = upt + (size_t)__ldg(user + b) * D_MODEL;
        const float* kc = g_K2 + tid;
        float s0 = 0.f, s1 = 0.f, s2 = 0.f, s3 = 0.f;
        #pragma unroll 4
        for (int c = 0; c < D_MODEL; c += 4) {
            s0 = fmaf(__ldg(ur + c + 0), __ldg(kc + (c + 0) * J_DIM), s0);
            s1 = fmaf(__ldg(ur + c + 1), __ldg(kc + (c + 1) * J_DIM), s1);
            s2 = fmaf(__ldg(ur + c + 2), __ldg(kc + (c + 2) * J_DIM), s2);
            s3 = fmaf(__ldg(ur + c + 3), __ldg(kc + (c + 3) * J_DIM), s3);
        }
        sUs[tid] = (s0 + s1) + (s2 + s3);
    }
    __syncthreads();

    // ---- phase 1: one (row, head) softmax per thread, stored as j-pairs ----
    {
        int r = tid >> 2, h = tid & 3;
        int n = n0 + r;
        int hh = __ldg(hour + n);
        int msk[T_SLOTS];
        const int4* mp = (const int4*)(hmask + (size_t)n * T_SLOTS);
        #pragma unroll
        for (int i = 0; i < 6; i++) {
            int4 q = mp[i];
            msk[4*i] = q.x; msk[4*i+1] = q.y; msk[4*i+2] = q.z; msk[4*i+3] = q.w;
        }
        const float* usb = sUs + h * T_SLOTS;
        const float* tsb = sTs + hh * J_DIM + h * T_SLOTS;
        float sc[T_SLOTS];
        float mx = -3.0e38f;
        #pragma unroll
        for (int t = 0; t < T_SLOTS; t++) {
            sc[t] = msk[t] ? -1e9f : (usb[t] + tsb[t]);
            mx = fmaxf(mx, sc[t]);
        }
        float s = 0.0f;
        #pragma unroll
        for (int t = 0; t < T_SLOTS; t++) {
            float e = __expf(sc[t] - mx);
            sc[t] = e; s += e;
        }
        float inv = 1.0f / s;
        u64* ar = sAtt + r * ATT_P + h * 12;     // j2 = h*12 + tt
        #pragma unroll
        for (int tt = 0; tt < 12; tt++)
            ar[tt] = pack2(sc[2*tt] * inv, sc[2*tt+1] * inv);
    }
    __syncthreads();

    // ---- phase 2: [64 x 96] @ [96 x 256] with j-pair packing ----
    int w = tid >> 5, l = tid & 31;
    int r0 = w * 8;

    // acc[rr][s]: f32 col = 2l + 64*(s>>1) + (s&1); u64 = (even-j, odd-j)
    u64 acc[8][8];
    #pragma unroll
    for (int i = 0; i < 4; i++) {
        float2 bv = __ldg((const float2*)bu + l + 32 * i);
        #pragma unroll
        for (int rr = 0; rr < 8; rr++) {
            acc[rr][2*i]   = pack2(bv.x, 0.f);
            acc[rr][2*i+1] = pack2(bv.y, 0.f);
        }
    }
    const ulonglong2* wp = (const ulonglong2*)sW2;  // 128 u128 per j2 row
    const u64* ap = sAtt + r0 * ATT_P;
    #pragma unroll 1
    for (int j2 = 0; j2 < J2; j2++) {
        ulonglong2 w0 = wp[j2 * 128 + l];
        ulonglong2 w1 = wp[j2 * 128 + l + 32];
        ulonglong2 w2 = wp[j2 * 128 + l + 64];
        ulonglong2 w3 = wp[j2 * 128 + l + 96];
        u64 a[8];
        #pragma unroll
        for (int rr = 0; rr < 8; rr++) a[rr] = ap[rr * ATT_P + j2];
        #pragma unroll
        for (int rr = 0; rr < 8; rr++) {
            fma2(acc[rr][0], a[rr], w0.x);
            fma2(acc[rr][1], a[rr], w0.y);
            fma2(acc[rr][2], a[rr], w1.x);
            fma2(acc[rr][3], a[rr], w1.y);
            fma2(acc[rr][4], a[rr], w2.x);
            fma2(acc[rr][5], a[rr], w2.y);
            fma2(acc[rr][6], a[rr], w3.x);
            fma2(acc[rr][7], a[rr], w3.y);
        }
    }
    #pragma unroll
    for (int rr = 0; rr < 8; rr++) {
        float2* orow = (float2*)(out + (size_t)(n0 + r0 + rr) * D_MODEL);
        #pragma unroll
        for (int i = 0; i < 4; i++) {
            float2 e0 = unpack2(acc[rr][2*i]);
            float2 e1 = unpack2(acc[rr][2*i+1]);
            orow[l + 32 * i] = make_float2(e0.x + e0.y, e1.x + e1.y);
        }
    }
}

extern "C" void kernel_launch(void* const* d_in, const int* in_sizes, int n_in,
                              void* d_out, int out_size) {
    const float* ts_emb = (const float*)d_in[0];
    const int*   user   = (const int*)  d_in[1];
    const int*   hour   = (const int*)  d_in[2];
    const int*   hmask  = (const int*)  d_in[3];
    const float* upt    = (const float*)d_in[4];
    const float* Wq     = (const float*)d_in[5];
    const float* bq     = (const float*)d_in[6];
    const float* Wk     = (const float*)d_in[7];
    const float* bk     = (const float*)d_in[8];
    const float* Wv     = (const float*)d_in[9];
    const float* bv     = (const float*)d_in[10];
    const float* Wu     = (const float*)d_in[11];
    const float* bu     = (const float*)d_in[12];
    float* out = (float*)d_out;

    pre1_kernel<<<168, 256>>>(ts_emb, Wq, bq, Wk, bk, Wv, bv, Wu);

    cudaFuncSetAttribute(main_kernel, cudaFuncAttributeMaxDynamicSharedMemorySize, SM_BYTES);
    main_kernel<<<N_ROWS / 64, 256, SM_BYTES>>>(hour, hmask, user, upt, bu, out);
}

// round 11
// speedup vs baseline: 1.1772x; 1.0108x over previous
#include <cuda_runtime.h>

// ---------------------------------------------------------------------------
// NextVisitTime attention, 2 launches:
//   pre1 : W2 j-PAIRS (inline v), ts (m-trick), K2 (inline k).
//   main : 32 rows/block, 2048 blocks, 2 blocks/SM: inline us, masked
//          softmax, then [32x96]@[96x256] fp32 GEMM via FFMA2 j-pair packing.
//          Weights read via LDG (L1-resident 96KB table) -> tiny smem ->
//          2 resident blocks -> 4 warps/SMSP latency hiding.
// ---------------------------------------------------------------------------

#define T_SLOTS 24
#define D_MODEL 256
#define B_BATCH 512
#define N_ROWS  65536
#define J_DIM   96
#define J2      48
#define HD      64

__device__ float g_ts [T_SLOTS * J_DIM];
__device__ float g_K2 [D_MODEL * J_DIM];             // scale folded in
__device__ unsigned long long g_W2p[J2 * D_MODEL];   // (W2[2k][c], W2[2k+1][c])

typedef unsigned long long u64;

__device__ __forceinline__ u64 pack2(float x, float y) {
    u64 r; asm("mov.b64 %0, {%1, %2};" : "=l"(r) : "f"(x), "f"(y)); return r;
}
__device__ __forceinline__ void fma2(u64 &c, u64 a, u64 b) {
    asm("fma.rn.f32x2 %0, %1, %2, %0;" : "+l"(c) : "l"(a), "l"(b));
}
__device__ __forceinline__ float2 unpack2(u64 v) {
    float2 r; asm("mov.b64 {%0, %1}, %2;" : "=f"(r.x), "=f"(r.y) : "l"(v)); return r;
}

// ===========================================================================
// PRE1: 168 independent blocks (unchanged — verified correct).
// ===========================================================================
__global__ __launch_bounds__(256) void pre1_kernel(
    const float* __restrict__ ts_emb,
    const float* __restrict__ Wq, const float* __restrict__ bq,
    const float* __restrict__ Wk, const float* __restrict__ bk,
    const float* __restrict__ Wv, const float* __restrict__ bv,
    const float* __restrict__ Wu)
{
    int bx = blockIdx.x, tid = threadIdx.x;

    if (bx < 48) {
        // ---- W2 pair: rows j0=2bx, j1=2bx+1 (h shared, t0, t1=t0+1) ----
        int j0 = 2 * bx;
        int h = j0 / T_SLOTS, t0 = j0 % T_SLOTS, t1 = t0 + 1;
        __shared__ __align__(16) float semb0[D_MODEL], semb1[D_MODEL];
        __shared__ __align__(16) float sv0[HD], sv1[HD];
        semb0[tid] = ts_emb[t0 * D_MODEL + tid];
        semb1[tid] = ts_emb[t1 * D_MODEL + tid];
        __syncthreads();
        float a0[4], a1[4];
        a0[0] = bv[tid]; a1[0] = a0[0];
        #pragma unroll
        for (int i = 1; i < 4; i++) { a0[i] = 0.f; a1[i] = 0.f; }
        #pragma unroll 4
        for (int c = 0; c < D_MODEL; c += 4) {
            #pragma unroll
            for (int u = 0; u < 4; u++) {
                float wv = Wv[(c + u) * D_MODEL + tid];
                a0[u] = fmaf(semb0[c + u], wv, a0[u]);
                a1[u] = fmaf(semb1[c + u], wv, a1[u]);
            }
        }
        float v0 = (a0[0] + a0[1]) + (a0[2] + a0[3]);
        float v1 = (a1[0] + a1[1]) + (a1[2] + a1[3]);
        if (tid >= h * HD && tid < h * HD + HD) {
            sv0[tid - h * HD] = v0;
            sv1[tid - h * HD] = v1;
        }
        __syncthreads();
        float b0[4], b1[4];
        #pragma unroll
        for (int i = 0; i < 4; i++) { b0[i] = 0.f; b1[i] = 0.f; }
        #pragma unroll 4
        for (int e = 0; e < HD; e += 4) {
            #pragma unroll
            for (int u = 0; u < 4; u++) {
                float wu = Wu[(h * HD + e + u) * D_MODEL + tid];
                b0[u] = fmaf(sv0[e + u], wu, b0[u]);
                b1[u] = fmaf(sv1[e + u], wu, b1[u]);
            }
        }
        float w0 = (b0[0] + b0[1]) + (b0[2] + b0[3]);
        float w1 = (b1[0] + b1[1]) + (b1[2] + b1[3]);
        g_W2p[bx * D_MODEL + tid] = pack2(w0, w1);

    } else if (bx < 72) {
        // ---- ts[th][h*24+t] = 0.125*(sum_c emb[t,c]*m[c,h] + tq.bk_h) ----
        int th = bx - 48;
        __shared__ __align__(16) float semb[D_MODEL];
        __shared__ __align__(16) float stq[D_MODEL];
        __shared__ __align__(16) float smm[D_MODEL * 4];
        __shared__ float stbk[4];
        semb[tid] = ts_emb[th * D_MODEL + tid];
        __syncthreads();
        float a[8];
        a[0] = bq[tid];
        #pragma unroll
        for (int i = 1; i < 8; i++) a[i] = 0.f;
        #pragma unroll 4
        for (int c = 0; c < D_MODEL; c += 8) {
            #pragma unroll
            for (int u = 0; u < 8; u++)
                a[u] = fmaf(semb[c + u], Wq[(D_MODEL + c + u) * D_MODEL + tid], a[u]);
        }
        stq[tid] = ((a[0]+a[1])+(a[2]+a[3])) + ((a[4]+a[5])+(a[6]+a[7]));
        __syncthreads();
        {
            const float4* wr = (const float4*)(Wk + (size_t)tid * D_MODEL);
            const float4* q4 = (const float4*)stq;
            #pragma unroll
            for (int h = 0; h < 4; h++) {
                float s0 = 0.f, s1 = 0.f, s2 = 0.f, s3 = 0.f;
                #pragma unroll 4
                for (int e4 = h * 16; e4 < h * 16 + 16; e4++) {
                    float4 wv = wr[e4], qv = q4[e4];
                    s0 = fmaf(qv.x, wv.x, s0); s1 = fmaf(qv.y, wv.y, s1);
                    s2 = fmaf(qv.z, wv.z, s2); s3 = fmaf(qv.w, wv.w, s3);
                }
                smm[tid * 4 + h] = (s0 + s1) + (s2 + s3);
            }
        }
        if (tid < 4) {
            float s = 0.f;
            for (int e = 0; e < HD; e++)
                s = fmaf(stq[tid * HD + e], bk[tid * HD + e], s);
            stbk[tid] = s;
        }
        __syncthreads();
        if (tid < J_DIM) {
            int h = tid / T_SLOTS, t = tid % T_SLOTS;
            const float* er = ts_emb + t * D_MODEL;
            float s0 = 0.f, s1 = 0.f, s2 = 0.f, s3 = 0.f;
            #pragma unroll 8
            for (int c = 0; c < D_MODEL; c += 4) {
                s0 = fmaf(er[c+0], smm[(c+0)*4 + h], s0);
                s1 = fmaf(er[c+1], smm[(c+1)*4 + h], s1);
                s2 = fmaf(er[c+2], smm[(c+2)*4 + h], s2);
                s3 = fmaf(er[c+3], smm[(c+3)*4 + h], s3);
            }
            g_ts[th * J_DIM + tid] =
                (((s0 + s1) + (s2 + s3)) + stbk[h]) * 0.125f;
        }

    } else {
        // ---- K2[c][j] = 0.125 * sum_e Wq0[c,h64+e] * k[t,h64+e] ----
        int j = bx - 72;
        int h = j / T_SLOTS, t = j % T_SLOTS;
        __shared__ __align__(16) float semb[D_MODEL];
        __shared__ float part[4][HD];
        __shared__ __align__(16) float kh[HD];
        semb[tid] = ts_emb[t * D_MODEL + tid];
        __syncthreads();
        {
            int e = tid & 63, ch = tid >> 6;
            const float* wk = Wk + (size_t)(ch * 64) * D_MODEL + h * HD + e;
            float s = 0.f;
            #pragma unroll 8
            for (int cc = 0; cc < 64; cc++)
                s = fmaf(semb[ch * 64 + cc], wk[cc * D_MODEL], s);
            part[ch][e] = s;
        }
        __syncthreads();
        if (tid < HD)
            kh[tid] = ((part[0][tid] + part[1][tid]) +
                       (part[2][tid] + part[3][tid])) + bk[h * HD + tid];
        __syncthreads();
        {
            const float4* wq = (const float4*)(Wq + (size_t)tid * D_MODEL + h * HD);
            const float4* k4 = (const float4*)kh;
            float s0 = 0.f, s1 = 0.f, s2 = 0.f, s3 = 0.f;
            #pragma unroll
            for (int e4 = 0; e4 < HD / 4; e4++) {
                float4 wv = wq[e4], kv = k4[e4];
                s0 = fmaf(wv.x, kv.x, s0); s1 = fmaf(wv.y, kv.y, s1);
                s2 = fmaf(wv.z, kv.z, s2); s3 = fmaf(wv.w, kv.w, s3);
            }
            g_K2[tid * J_DIM + j] = ((s0 + s1) + (s2 + s3)) * 0.125f;
        }
    }
}

// ===========================================================================
// MAIN: 256 threads, 32 rows/block, 2048 blocks, 2 blocks/SM.
// SMEM (static, ~22KB): att u64 32 x 49 | ts 2304 | us 96
// Phase 2: warp w -> rowgroup w>>1 (8 rows), colhalf ch = w&1.
//   Thread: 8 rows x 4 f32 cols (u64 pair-cols c0 = ch*64+l, c1 = c0+32).
//   Weights via __ldg (L1-resident 96KB W2p); att via warp-uniform LDS.64.
//   acc = 32 u64 = 64 regs -> fits 2 blocks/SM.
// ===========================================================================
#define ATT_P 49                                     // u64 pitch per row

__global__ __launch_bounds__(256, 2) void main_kernel(
    const int* __restrict__ hour, const int* __restrict__ hmask,
    const int* __restrict__ user, const float* __restrict__ upt,
    const float* __restrict__ bu, float* __restrict__ out)
{
    __shared__ __align__(16) u64   sAtt[32 * ATT_P];
    __shared__ __align__(16) float sTs[T_SLOTS * J_DIM];
    __shared__ __align__(16) float sUs[J_DIM];

    int tid = threadIdx.x;
    int n0  = blockIdx.x * 32;
    int b   = blockIdx.x >> 2;         // 4 blocks per batch row

    // cooperative ts load + inline us[b] = upt[user[b]] @ K2
    {
        const float4* s2 = (const float4*)g_ts;
        float4* d2 = (float4*)sTs;
        for (int i = tid; i < (T_SLOTS * J_DIM) / 4; i += 256) d2[i] = s2[i];
    }
    if (tid < J_DIM) {
        const float* ur = upt + (size_t)__ldg(user + b) * D_MODEL;
        const float* kc = g_K2 + tid;
        float s0 = 0.f, s1 = 0.f, s2 = 0.f, s3 = 0.f;
        #pragma unroll 4
        for (int c = 0; c < D_MODEL; c += 4) {
            s0 = fmaf(__ldg(ur + c + 0), __ldg(kc + (c + 0) * J_DIM), s0);
            s1 = fmaf(__ldg(ur + c + 1), __ldg(kc + (c + 1) * J_DIM), s1);
            s2 = fmaf(__ldg(ur + c + 2), __ldg(kc + (c + 2) * J_DIM), s2);
            s3 = fmaf(__ldg(ur + c + 3), __ldg(kc + (c + 3) * J_DIM), s3);
        }
        sUs[tid] = (s0 + s1) + (s2 + s3);
    }
    __syncthreads();

    // ---- phase 1: threads [0,128): one (row, head) softmax, j-pair store ----
    if (tid < 128) {
        int r = tid >> 2, h = tid & 3;
        int n = n0 + r;
        int hh = __ldg(hour + n);
        int msk[T_SLOTS];
        const int4* mp = (const int4*)(hmask + (size_t)n * T_SLOTS);
        #pragma unroll
        for (int i = 0; i < 6; i++) {
            int4 q = mp[i];
            msk[4*i] = q.x; msk[4*i+1] = q.y; msk[4*i+2] = q.z; msk[4*i+3] = q.w;
        }
        const float* usb = sUs + h * T_SLOTS;
        const float* tsb = sTs + hh * J_DIM + h * T_SLOTS;
        float sc[T_SLOTS];
        float mx = -3.0e38f;
        #pragma unroll
        for (int t = 0; t < T_SLOTS; t++) {
            sc[t] = msk[t] ? -1e9f : (usb[t] + tsb[t]);
            mx = fmaxf(mx, sc[t]);
        }
        float s = 0.0f;
        #pragma unroll
        for (int t = 0; t < T_SLOTS; t++) {
            float e = __expf(sc[t] - mx);
            sc[t] = e; s += e;
        }
        float inv = 1.0f / s;
        u64* ar = sAtt + r * ATT_P + h * 12;   // j2 = h*12 + tt
        #pragma unroll
        for (int tt = 0; tt < 12; tt++)
            ar[tt] = pack2(sc[2*tt] * inv, sc[2*tt+1] * inv);
    }
    __syncthreads();

    // ---- phase 2: [32 x 96] @ [96 x 256] with j-pair packing ----
    int w = tid >> 5, l = tid & 31;
    int rg = w >> 1, ch = w & 1;
    int r0 = rg * 8;
    int c0 = ch * 64 + l;               // u64 pair-col, second = c0 + 32

    u64 acc[8][4];
    {
        float2 b0 = __ldg((const float2*)bu + c0);
        float2 b1 = __ldg((const float2*)bu + c0 + 32);
        #pragma unroll
        for (int rr = 0; rr < 8; rr++) {
            acc[rr][0] = pack2(b0.x, 0.f);
            acc[rr][1] = pack2(b0.y, 0.f);
            acc[rr][2] = pack2(b1.x, 0.f);
            acc[rr][3] = pack2(b1.y, 0.f);
        }
    }
    const ulonglong2* gW = (const ulonglong2*)g_W2p;  // 128 u128 per j2 row
    const u64* ap = sAtt + r0 * ATT_P;
    #pragma unroll 2
    for (int j2 = 0; j2 < J2; j2++) {
        ulonglong2 w0 = __ldg(gW + j2 * 128 + c0);
        ulonglong2 w1 = __ldg(gW + j2 * 128 + c0 + 32);
        u64 a[8];
        #pragma unroll
        for (int rr = 0; rr < 8; rr++) a[rr] = ap[rr * ATT_P + j2];
        #pragma unroll
        for (int rr = 0; rr < 8; rr++) {
            fma2(acc[rr][0], a[rr], w0.x);
            fma2(acc[rr][1], a[rr], w0.y);
            fma2(acc[rr][2], a[rr], w1.x);
            fma2(acc[rr][3], a[rr], w1.y);
        }
    }
    #pragma unroll
    for (int rr = 0; rr < 8; rr++) {
        float2* orow = (float2*)(out + (size_t)(n0 + r0 + rr) * D_MODEL);
        float2 e0 = unpack2(acc[rr][0]);
        float2 e1 = unpack2(acc[rr][1]);
        float2 e2 = unpack2(acc[rr][2]);
        float2 e3 = unpack2(acc[rr][3]);
        orow[c0]      = make_float2(e0.x + e0.y, e1.x + e1.y);
        orow[c0 + 32] = make_float2(e2.x + e2.y, e3.x + e3.y);
    }
}

extern "C" void kernel_launch(void* const* d_in, const int* in_sizes, int n_in,
                              void* d_out, int out_size) {
    const float* ts_emb = (const float*)d_in[0];
    const int*   user   = (const int*)  d_in[1];
    const int*   hour   = (const int*)  d_in[2];
    const int*   hmask  = (const int*)  d_in[3];
    const float* upt    = (const float*)d_in[4];
    const float* Wq     = (const float*)d_in[5];
    const float* bq     = (const float*)d_in[6];
    const float* Wk     = (const float*)d_in[7];
    const float* bk     = (const float*)d_in[8];
    const float* Wv     = (const float*)d_in[9];
    const float* bv     = (const float*)d_in[10];
    const float* Wu     = (const float*)d_in[11];
    const float* bu     = (const float*)d_in[12];
    float* out = (float*)d_out;

    pre1_kernel<<<168, 256>>>(ts_emb, Wq, bq, Wk, bk, Wv, bv, Wu);

    main_kernel<<<N_ROWS / 32, 256>>>(hour, hmask, user, upt, bu, out);
}

// round 12
// speedup vs baseline: 1.2245x; 1.0402x over previous
#include <cuda_runtime.h>

// ---------------------------------------------------------------------------
// NextVisitTime attention, 3 launches:
//   pre1 : W2 j-PAIRS (inline v), ts (m-trick), K2 (inline k).
//   preC : us[b] = upt[user[b]] @ K2 (8 users/block).
//   main : 32 rows/block, 2048 blocks, 2 blocks/SM: masked softmax, then
//          [32x96]@[96x256] fp32 GEMM, FFMA2 j-pair packing. Weights via
//          LDG (L1-resident 96KB), att via uniform LDS.128 j2-PAIRS
//          -> 24 wf per 128 FMA cyc per warp: FMA-bound with L1 slack.
// ---------------------------------------------------------------------------

#define T_SLOTS 24
#define D_MODEL 256
#define B_BATCH 512
#define N_ROWS  65536
#define J_DIM   96
#define J2      48
#define HD      64

__device__ float g_ts [T_SLOTS * J_DIM];
__device__ float g_K2 [D_MODEL * J_DIM];             // scale folded in
__device__ float g_us [B_BATCH * J_DIM];
__device__ unsigned long long g_W2p[J2 * D_MODEL];   // (W2[2k][c], W2[2k+1][c])

typedef unsigned long long u64;

__device__ __forceinline__ u64 pack2(float x, float y) {
    u64 r; asm("mov.b64 %0, {%1, %2};" : "=l"(r) : "f"(x), "f"(y)); return r;
}
__device__ __forceinline__ void fma2(u64 &c, u64 a, u64 b) {
    asm("fma.rn.f32x2 %0, %1, %2, %0;" : "+l"(c) : "l"(a), "l"(b));
}
__device__ __forceinline__ float2 unpack2(u64 v) {
    float2 r; asm("mov.b64 {%0, %1}, %2;" : "=f"(r.x), "=f"(r.y) : "l"(v)); return r;
}

// ===========================================================================
// PRE1: 168 independent blocks (unchanged — verified correct).
// ===========================================================================
__global__ __launch_bounds__(256) void pre1_kernel(
    const float* __restrict__ ts_emb,
    const float* __restrict__ Wq, const float* __restrict__ bq,
    const float* __restrict__ Wk, const float* __restrict__ bk,
    const float* __restrict__ Wv, const float* __restrict__ bv,
    const float* __restrict__ Wu)
{
    int bx = blockIdx.x, tid = threadIdx.x;

    if (bx < 48) {
        // ---- W2 pair: rows j0=2bx, j1=2bx+1 (h shared, t0, t1=t0+1) ----
        int j0 = 2 * bx;
        int h = j0 / T_SLOTS, t0 = j0 % T_SLOTS, t1 = t0 + 1;
        __shared__ __align__(16) float semb0[D_MODEL], semb1[D_MODEL];
        __shared__ __align__(16) float sv0[HD], sv1[HD];
        semb0[tid] = ts_emb[t0 * D_MODEL + tid];
        semb1[tid] = ts_emb[t1 * D_MODEL + tid];
        __syncthreads();
        float a0[4], a1[4];
        a0[0] = bv[tid]; a1[0] = a0[0];
        #pragma unroll
        for (int i = 1; i < 4; i++) { a0[i] = 0.f; a1[i] = 0.f; }
        #pragma unroll 4
        for (int c = 0; c < D_MODEL; c += 4) {
            #pragma unroll
            for (int u = 0; u < 4; u++) {
                float wv = Wv[(c + u) * D_MODEL + tid];
                a0[u] = fmaf(semb0[c + u], wv, a0[u]);
                a1[u] = fmaf(semb1[c + u], wv, a1[u]);
            }
        }
        float v0 = (a0[0] + a0[1]) + (a0[2] + a0[3]);
        float v1 = (a1[0] + a1[1]) + (a1[2] + a1[3]);
        if (tid >= h * HD && tid < h * HD + HD) {
            sv0[tid - h * HD] = v0;
            sv1[tid - h * HD] = v1;
        }
        __syncthreads();
        float b0[4], b1[4];
        #pragma unroll
        for (int i = 0; i < 4; i++) { b0[i] = 0.f; b1[i] = 0.f; }
        #pragma unroll 4
        for (int e = 0; e < HD; e += 4) {
            #pragma unroll
            for (int u = 0; u < 4; u++) {
                float wu = Wu[(h * HD + e + u) * D_MODEL + tid];
                b0[u] = fmaf(sv0[e + u], wu, b0[u]);
                b1[u] = fmaf(sv1[e + u], wu, b1[u]);
            }
        }
        float w0 = (b0[0] + b0[1]) + (b0[2] + b0[3]);
        float w1 = (b1[0] + b1[1]) + (b1[2] + b1[3]);
        g_W2p[bx * D_MODEL + tid] = pack2(w0, w1);

    } else if (bx < 72) {
        // ---- ts[th][h*24+t] = 0.125*(sum_c emb[t,c]*m[c,h] + tq.bk_h) ----
        int th = bx - 48;
        __shared__ __align__(16) float semb[D_MODEL];
        __shared__ __align__(16) float stq[D_MODEL];
        __shared__ __align__(16) float smm[D_MODEL * 4];
        __shared__ float stbk[4];
        semb[tid] = ts_emb[th * D_MODEL + tid];
        __syncthreads();
        float a[8];
        a[0] = bq[tid];
        #pragma unroll
        for (int i = 1; i < 8; i++) a[i] = 0.f;
        #pragma unroll 4
        for (int c = 0; c < D_MODEL; c += 8) {
            #pragma unroll
            for (int u = 0; u < 8; u++)
                a[u] = fmaf(semb[c + u], Wq[(D_MODEL + c + u) * D_MODEL + tid], a[u]);
        }
        stq[tid] = ((a[0]+a[1])+(a[2]+a[3])) + ((a[4]+a[5])+(a[6]+a[7]));
        __syncthreads();
        {
            const float4* wr = (const float4*)(Wk + (size_t)tid * D_MODEL);
            const float4* q4 = (const float4*)stq;
            #pragma unroll
            for (int h = 0; h < 4; h++) {
                float s0 = 0.f, s1 = 0.f, s2 = 0.f, s3 = 0.f;
                #pragma unroll 4
                for (int e4 = h * 16; e4 < h * 16 + 16; e4++) {
                    float4 wv = wr[e4], qv = q4[e4];
                    s0 = fmaf(qv.x, wv.x, s0); s1 = fmaf(qv.y, wv.y, s1);
                    s2 = fmaf(qv.z, wv.z, s2); s3 = fmaf(qv.w, wv.w, s3);
                }
                smm[tid * 4 + h] = (s0 + s1) + (s2 + s3);
            }
        }
        if (tid < 4) {
            float s = 0.f;
            for (int e = 0; e < HD; e++)
                s = fmaf(stq[tid * HD + e], bk[tid * HD + e], s);
            stbk[tid] = s;
        }
        __syncthreads();
        if (tid < J_DIM) {
            int h = tid / T_SLOTS, t = tid % T_SLOTS;
            const float* er = ts_emb + t * D_MODEL;
            float s0 = 0.f, s1 = 0.f, s2 = 0.f, s3 = 0.f;
            #pragma unroll 8
            for (int c = 0; c < D_MODEL; c += 4) {
                s0 = fmaf(er[c+0], smm[(c+0)*4 + h], s0);
                s1 = fmaf(er[c+1], smm[(c+1)*4 + h], s1);
                s2 = fmaf(er[c+2], smm[(c+2)*4 + h], s2);
                s3 = fmaf(er[c+3], smm[(c+3)*4 + h], s3);
            }
            g_ts[th * J_DIM + tid] =
                (((s0 + s1) + (s2 + s3)) + stbk[h]) * 0.125f;
        }

    } else {
        // ---- K2[c][j] = 0.125 * sum_e Wq0[c,h64+e] * k[t,h64+e] ----
        int j = bx - 72;
        int h = j / T_SLOTS, t = j % T_SLOTS;
        __shared__ __align__(16) float semb[D_MODEL];
        __shared__ float part[4][HD];
        __shared__ __align__(16) float kh[HD];
        semb[tid] = ts_emb[t * D_MODEL + tid];
        __syncthreads();
        {
            int e = tid & 63, ch = tid >> 6;
            const float* wk = Wk + (size_t)(ch * 64) * D_MODEL + h * HD + e;
            float s = 0.f;
            #pragma unroll 8
            for (int cc = 0; cc < 64; cc++)
                s = fmaf(semb[ch * 64 + cc], wk[cc * D_MODEL], s);
            part[ch][e] = s;
        }
        __syncthreads();
        if (tid < HD)
            kh[tid] = ((part[0][tid] + part[1][tid]) +
                       (part[2][tid] + part[3][tid])) + bk[h * HD + tid];
        __syncthreads();
        {
            const float4* wq = (const float4*)(Wq + (size_t)tid * D_MODEL + h * HD);
            const float4* k4 = (const float4*)kh;
            float s0 = 0.f, s1 = 0.f, s2 = 0.f, s3 = 0.f;
            #pragma unroll
            for (int e4 = 0; e4 < HD / 4; e4++) {
                float4 wv = wq[e4], kv = k4[e4];
                s0 = fmaf(wv.x, kv.x, s0); s1 = fmaf(wv.y, kv.y, s1);
                s2 = fmaf(wv.z, kv.z, s2); s3 = fmaf(wv.w, kv.w, s3);
            }
            g_K2[tid * J_DIM + j] = ((s0 + s1) + (s2 + s3)) * 0.125f;
        }
    }
}

// ===========================================================================
// PREC: us[b] = upt[user[b]] @ K2  (8 users per block, 96 threads) — proven.
// ===========================================================================
__global__ __launch_bounds__(96) void preC_kernel(const int* __restrict__ user,
                                                  const float* __restrict__ upt)
{
    __shared__ float srow[8][D_MODEL];
    int b0 = blockIdx.x * 8;
    int j  = threadIdx.x;            // 0..95
    #pragma unroll
    for (int i = 0; i < 8; i++) {
        const float* src = upt + (size_t)__ldg(user + b0 + i) * D_MODEL;
        for (int d = j; d < D_MODEL; d += 96) srow[i][d] = src[d];
    }
    __syncthreads();
    float acc[8];
    #pragma unroll
    for (int i = 0; i < 8; i++) acc[i] = 0.0f;
    #pragma unroll 8
    for (int c = 0; c < D_MODEL; c++) {
        float w = g_K2[c * J_DIM + j];
        #pragma unroll
        for (int i = 0; i < 8; i++) acc[i] = fmaf(srow[i][c], w, acc[i]);
    }
    #pragma unroll
    for (int i = 0; i < 8; i++) g_us[(b0 + i) * J_DIM + j] = acc[i];
}

// ===========================================================================
// MAIN: 256 threads, 32 rows/block, 2048 blocks, 2 blocks/SM.
// SMEM (static, ~23KB): att u64 32 x 50 | ts 2304 | us 96
// Phase 2: warp w -> rowgroup w>>1 (8 rows), colhalf ch = w&1; thread =
//   8 rows x 4 f32 cols. Weights via __ldg (L1-resident W2p); att via
//   UNIFORM LDS.128 j2-pairs (1 wf covers 2 j2). 24 wf / 128 FMA cyc /warp.
// ===========================================================================
#define ATT_P 50                                     // u64 pitch (even: 16B align)

__global__ __launch_bounds__(256, 2) void main_kernel(
    const int* __restrict__ hour, const int* __restrict__ hmask,
    const float* __restrict__ bu, float* __restrict__ out)
{
    __shared__ __align__(16) u64   sAtt[32 * ATT_P];
    __shared__ __align__(16) float sTs[T_SLOTS * J_DIM];
    __shared__ __align__(16) float sUs[J_DIM];

    int tid = threadIdx.x;
    int n0  = blockIdx.x * 32;
    int b   = blockIdx.x >> 2;         // 4 blocks per batch row

    // cooperative ts + us loads
    {
        const float4* s2 = (const float4*)g_ts;
        float4* d2 = (float4*)sTs;
        for (int i = tid; i < (T_SLOTS * J_DIM) / 4; i += 256) d2[i] = s2[i];
        if (tid < J_DIM / 4)
            ((float4*)sUs)[tid] = ((const float4*)(g_us + b * J_DIM))[tid];
    }
    __syncthreads();

    // ---- phase 1: threads [0,128): one (row, head) softmax, j-pair store ----
    if (tid < 128) {
        int r = tid >> 2, h = tid & 3;
        int n = n0 + r;
        int hh = __ldg(hour + n);
        int msk[T_SLOTS];
        const int4* mp = (const int4*)(hmask + (size_t)n * T_SLOTS);
        #pragma unroll
        for (int i = 0; i < 6; i++) {
            int4 q = mp[i];
            msk[4*i] = q.x; msk[4*i+1] = q.y; msk[4*i+2] = q.z; msk[4*i+3] = q.w;
        }
        const float* usb = sUs + h * T_SLOTS;
        const float* tsb = sTs + hh * J_DIM + h * T_SLOTS;
        float sc[T_SLOTS];
        float mx = -3.0e38f;
        #pragma unroll
        for (int t = 0; t < T_SLOTS; t++) {
            sc[t] = msk[t] ? -1e9f : (usb[t] + tsb[t]);
            mx = fmaxf(mx, sc[t]);
        }
        float s = 0.0f;
        #pragma unroll
        for (int t = 0; t < T_SLOTS; t++) {
            float e = __expf(sc[t] - mx);
            sc[t] = e; s += e;
        }
        float inv = 1.0f / s;
        u64* ar = sAtt + r * ATT_P + h * 12;   // j2 = h*12 + tt
        #pragma unroll
        for (int tt = 0; tt < 12; tt++)
            ar[tt] = pack2(sc[2*tt] * inv, sc[2*tt+1] * inv);
    }
    __syncthreads();

    // ---- phase 2: [32 x 96] @ [96 x 256], j2 processed in pairs ----
    int w = tid >> 5, l = tid & 31;
    int rg = w >> 1, ch = w & 1;
    int r0 = rg * 8;
    int c0 = ch * 64 + l;               // u64 pair-col, second = c0 + 32

    u64 acc[8][4];
    {
        float2 b0 = __ldg((const float2*)bu + c0);
        float2 b1 = __ldg((const float2*)bu + c0 + 32);
        #pragma unroll
        for (int rr = 0; rr < 8; rr++) {
            acc[rr][0] = pack2(b0.x, 0.f);
            acc[rr][1] = pack2(b0.y, 0.f);
            acc[rr][2] = pack2(b1.x, 0.f);
            acc[rr][3] = pack2(b1.y, 0.f);
        }
    }
    const ulonglong2* gW  = (const ulonglong2*)g_W2p;      // 128 u128 / j2 row
    const ulonglong2* ap2 = (const ulonglong2*)(sAtt + r0 * ATT_P);
    #pragma unroll 1
    for (int jp = 0; jp < J2 / 2; jp++) {
        int j2 = 2 * jp;
        ulonglong2 wA0 = __ldg(gW + j2 * 128 + c0);
        ulonglong2 wA1 = __ldg(gW + j2 * 128 + c0 + 32);
        ulonglong2 wB0 = __ldg(gW + (j2 + 1) * 128 + c0);
        ulonglong2 wB1 = __ldg(gW + (j2 + 1) * 128 + c0 + 32);
        #pragma unroll
        for (int rr = 0; rr < 8; rr++) {
            ulonglong2 a = ap2[rr * (ATT_P / 2) + jp];     // (j2, j2+1) pair
            fma2(acc[rr][0], a.x, wA0.x);
            fma2(acc[rr][1], a.x, wA0.y);
            fma2(acc[rr][2], a.x, wA1.x);
            fma2(acc[rr][3], a.x, wA1.y);
            fma2(acc[rr][0], a.y, wB0.x);
            fma2(acc[rr][1], a.y, wB0.y);
            fma2(acc[rr][2], a.y, wB1.x);
            fma2(acc[rr][3], a.y, wB1.y);
        }
    }
    #pragma unroll
    for (int rr = 0; rr < 8; rr++) {
        float2* orow = (float2*)(out + (size_t)(n0 + r0 + rr) * D_MODEL);
        float2 e0 = unpack2(acc[rr][0]);
        float2 e1 = unpack2(acc[rr][1]);
        float2 e2 = unpack2(acc[rr][2]);
        float2 e3 = unpack2(acc[rr][3]);
        orow[c0]      = make_float2(e0.x + e0.y, e1.x + e1.y);
        orow[c0 + 32] = make_float2(e2.x + e2.y, e3.x + e3.y);
    }
}

extern "C" void kernel_launch(void* const* d_in, const int* in_sizes, int n_in,
                              void* d_out, int out_size) {
    const float* ts_emb = (const float*)d_in[0];
    const int*   user   = (const int*)  d_in[1];
    const int*   hour   = (const int*)  d_in[2];
    const int*   hmask  = (const int*)  d_in[3];
    const float* upt    = (const float*)d_in[4];
    const float* Wq     = (const float*)d_in[5];
    const float* bq     = (const float*)d_in[6];
    const float* Wk     = (const float*)d_in[7];
    const float* bk     = (const float*)d_in[8];
    const float* Wv     = (const float*)d_in[9];
    const float* bv     = (const float*)d_in[10];
    const float* Wu     = (const float*)d_in[11];
    const float* bu     = (const float*)d_in[12];
    float* out = (float*)d_out;

    pre1_kernel<<<168, 256>>>(ts_emb, Wq, bq, Wk, bk, Wv, bv, Wu);
    preC_kernel<<<B_BATCH / 8, 96>>>(user, upt);

    main_kernel<<<N_ROWS / 32, 256>>>(hour, hmask, bu, out);
}